// round 13
// baseline (speedup 1.0000x reference)
#include <cuda_runtime.h>

#define CUT  14
#define DIM  2744          // 14^3
#define SECT 1834          // sum over sectors of c(s)^2
#define BSPAD 1840         // SECT padded to float4 multiple
#define NT   448           // evolve threads per CTA

// ---------------- persistent device scratch (no allocs allowed) ----------------
__device__ float  g_bsR[24][BSPAD];      // 24 BS gates: REAL sector-packed rotation
__device__ float  g_smR[24][CUT*CUT];    // 24 REAL single-mode gates (Sreal/Dreal)
__device__ float2 g_wrow[24][CUT];       // BS writeback phase (output row)
__device__ float2 g_wcol[24][CUT];       // BS writeback phase (output col)
__device__ float2 g_wfib[24][CUT];       // BS writeback phase (fiber; p1 only)
__device__ float2 g_sdiag[24][CUT];      // single-mode writeback diagonal
__device__ float2 g_init[2][CUT];        // initial-state phase on n0
__device__ float  g_dvec[2][1024][3][CUT]; // initial displacement vectors (real)

// ---------------- packed f32x2 helpers ----------------
__device__ __forceinline__ unsigned long long pk2(float lo, float hi) {
  unsigned long long r;
  asm("mov.b64 %0, {%1, %2};" : "=l"(r) : "f"(lo), "f"(hi));
  return r;
}
__device__ __forceinline__ void upk2(unsigned long long v, float& lo, float& hi) {
  asm("mov.b64 {%0, %1}, %2;" : "=f"(lo), "=f"(hi) : "l"(v));
}
__device__ __forceinline__ unsigned long long f2fma(unsigned long long a,
                                                    unsigned long long b,
                                                    unsigned long long c) {
  unsigned long long d;
  asm("fma.rn.f32x2 %0, %1, %2, %3;" : "=l"(d) : "l"(a), "l"(b), "l"(c));
  return d;
}

// ================= gate precompute: fp32 expm (s=8, terms=12, banded Taylor) =================
// ALL gates are real matrices; phases live in writeback-diagonal vectors:
//   BS:      U = e^{i phi n_m} Rreal e^{-i phi n_m}
//   squeeze: S = e^{i phr n/2} Sreal e^{-i phr n/2};  M1 = S*R(vph1)
//   disp:    D = e^{i pha n}   Dreal e^{-i pha n};    M2 = K*D*R(vph2)
__global__ void __launch_bounds__(196) gates_kernel(
    const float* __restrict__ th1, const float* __restrict__ ph1,
    const float* __restrict__ vph1, const float* __restrict__ rr,
    const float* __restrict__ phr, const float* __restrict__ th2,
    const float* __restrict__ ph2, const float* __restrict__ vph2,
    const float* __restrict__ aa, const float* __restrict__ pha,
    const float* __restrict__ kk)
{
  __shared__ float2 Bm[196], Ta[196], Tb[196], Ot[196];
  const int tid = threadIdx.x;
  const int i = tid / CUT, j = tid % CUT;
  const int task = blockIdx.x;

  int c = CUT, s = 0, pm = 0, gid = -1;
  double2 h = make_double2(0.0, 0.0);

  if (task < 648) {
    gid = task / 27; s = task % 27;
    pm = (s < CUT) ? 0 : s - (CUT-1);
    c  = (s < CUT) ? s + 1 : 2*CUT - 1 - s;
    int circ = gid / 12, rem = gid % 12;
    int l = rem / 6, w = (rem / 3) % 2, p = rem % 3;
    int b3 = (circ*2 + l)*3;
    double th = (double)((w ? th2 : th1)[b3 + p]);

    // writeback phase vectors (once per gate, via the s==0 block)
    if (s == 0 && tid < CUT) {
      const float* php = w ? ph2 : ph1;
      double f0 = (double)php[b3+0], f1v = (double)php[b3+1], f2v = (double)php[b3+2];
      double n = (double)tid;
      double dpn0, dpn1, dpn2;   // pre-diagonal angles of the NEXT single-mode gates
      if (w == 0) {
        dpn0 = ((double)vph1[b3+0] - 0.5*(double)phr[b3+0]) * n;
        dpn1 = ((double)vph1[b3+1] - 0.5*(double)phr[b3+1]) * n;
        dpn2 = ((double)vph1[b3+2] - 0.5*(double)phr[b3+2]) * n;
      } else {
        dpn0 = ((double)vph2[b3+0] - (double)pha[b3+0]) * n;
        dpn1 = ((double)vph2[b3+1] - (double)pha[b3+1]) * n;
        dpn2 = ((double)vph2[b3+2] - (double)pha[b3+2]) * n;
      }
      double ar, ac, af = 0.0;
      if (p == 0)      { ar = f0*n;          ac = -f1v*n; }
      else if (p == 1) { ar = f1v*n;         ac = dpn2;   af = -f2v*n; }
      else             { ar = f2v*n + dpn0;  ac = dpn1;   }
      g_wrow[gid][tid] = make_float2((float)cos(ar), (float)sin(ar));
      g_wcol[gid][tid] = make_float2((float)cos(ac), (float)sin(ac));
      g_wfib[gid][tid] = make_float2((float)cos(af), (float)sin(af));
      if (l == 0 && w == 0 && p == 0)
        g_init[circ][tid] = make_float2((float)cos(f0*n), (float)(-sin(f0*n)));
    }

    if (i < c && j < c) {
      int P = pm + i, Q = s - P;
      if (j == i - 1)      h.x =  th * sqrt((double)P * (double)(Q + 1));
      else if (j == i + 1) h.x = -th * sqrt((double)(P + 1) * (double)Q);
    }
  } else {
    int u = task - 648;
    int circ = u / 12, rem = u % 12;
    int l = rem / 6, w = (rem / 3) % 2, m = rem % 3;
    int pi = (circ*2 + l)*3 + m;
    if (w == 0) {  // Sreal = expm(r/2 (A^2 - Ad^2))
      double rv = (double)rr[pi];
      if (j == i + 2)      h.x =  0.5*sqrt((double)(i+1)*(double)(i+2))*rv;
      else if (i == j + 2) h.x = -0.5*sqrt((double)(j+1)*(double)(j+2))*rv;
    } else {       // Dreal = expm(a (Ad - A))
      double av = (double)aa[pi];
      if (i == j + 1)      h.x =  sqrt((double)j+1.0)*av;
      else if (j == i + 1) h.x = -sqrt((double)i+1.0)*av;
    }
    // writeback diagonal for this single-mode gate
    if (tid < CUT) {
      double n = (double)tid, ang;
      if (w == 0) {
        ang = 0.5*(double)phr[pi]*n;                    // post of S
        if (m == 0) ang -= (double)ph2[(circ*2 + l)*3 + 0]*n;  // pre of next BS set (mode0)
      } else {
        ang = (double)kk[pi]*n*n + (double)pha[pi]*n;   // K and post of D
        if (m == 0 && l == 0) ang -= (double)ph1[(circ*2 + 1)*3 + 0]*n;  // pre of layer-1 BS
      }
      g_sdiag[u][tid] = make_float2((float)cos(ang), (float)sin(ang));
    }
  }

  const bool act = (i < c && j < c);
  const double sc = 1.0/256.0;   // 2^-8
  Bm[tid] = make_float2((float)(h.x*sc), (float)(h.y*sc));
  float idv = (act && i == j) ? 1.0f : 0.0f;
  Ta[tid] = make_float2(idv, 0.0f);
  Ot[tid] = make_float2(idv, 0.0f);
  __syncthreads();

  const int t_lo = (j >= 2) ? j - 2 : 0;
  float2* term = Ta; float2* nxt = Tb;
  for (int k = 1; k <= 12; k++) {
    float2 acc = make_float2(0.f, 0.f);
    if (act) {
      int t_hi = (j + 2 < c - 1) ? j + 2 : c - 1;
      for (int t = t_lo; t <= t_hi; t++) {
        float2 xv = term[i*CUT + t], yv = Bm[t*CUT + j];
        acc.x += xv.x*yv.x - xv.y*yv.y;
        acc.y += xv.x*yv.y + xv.y*yv.x;
      }
      float inv = 1.0f/(float)k;
      acc.x *= inv; acc.y *= inv;
      nxt[i*CUT + j] = acc;
      Ot[i*CUT + j].x += acc.x;
      Ot[i*CUT + j].y += acc.y;
    }
    float2* z = term; term = nxt; nxt = z;
    __syncthreads();
  }
  for (int q = 0; q < 8; q++) {   // 8 squarings (2^8 scaling)
    float2 acc = make_float2(0.f, 0.f);
    if (act) {
      for (int t = 0; t < c; t++) {
        float2 xv = Ot[i*CUT + t], yv = Ot[t*CUT + j];
        acc.x += xv.x*yv.x - xv.y*yv.y;
        acc.y += xv.x*yv.y + xv.y*yv.x;
      }
    }
    __syncthreads();
    if (act) Ot[i*CUT + j] = acc;
    __syncthreads();
  }

  if (task < 648) {
    if (act) {
      int off = (s < CUT) ? s*(s+1)*(2*s+1)/6
                          : SECT - ((27-s)*(28-s)*(55-2*s))/6;
      g_bsR[gid][off + i*c + j] = Ot[tid].x;
    }
  } else {
    g_smR[task - 648][tid] = Ot[tid].x;
  }
}

// ============ initial displacement vectors: coherent-state closed form ============
__global__ void __launch_bounds__(256) dvec_kernel(const float* __restrict__ x)
{
  int tid = blockIdx.x*blockDim.x + threadIdx.x;
  if (tid >= 1024*6) return;
  int b = tid / 6, colx = tid % 6, circ = colx / 3, m = colx % 3;
  double xv = (double)x[tid];
  double c = exp(-0.5 * xv * xv);
  #pragma unroll
  for (int n = 0; n < CUT; n++) {
    g_dvec[circ][b][m][n] = (float)c;
    c *= xv * rsqrt((double)(n + 1));
  }
}

// ================= main evolution: one CTA per (batch, circuit) =================
__global__ void __launch_bounds__(NT, 4) evolve_kernel(float* __restrict__ out)
{
  __shared__ unsigned long long spl[DIM];       // state, (re,im) packed
  __shared__ unsigned long long sgd[BSPAD];     // staged gate, (w,w) duplicated
  __shared__ float2 swr[CUT], swc[CUT], swf[CUT], ssd[CUT], ph0s[CUT];
  __shared__ float  sd[3*CUT];
  __shared__ float  sred[3][NT/32];

  float2* sp = (float2*)spl;
  const int tid = threadIdx.x;
  const int b = blockIdx.x, circ = blockIdx.y;

  if (tid < 3*CUT) sd[tid] = g_dvec[circ][b][tid/CUT][tid%CUT];
  else if (tid < 4*CUT) ph0s[tid - 3*CUT] = g_init[circ][tid - 3*CUT];
  __syncthreads();
  for (int idx = tid; idx < DIM; idx += NT) {
    int i0 = idx / 196, j0 = (idx / CUT) % CUT, k0 = idx % CUT;
    float prod = sd[i0]*sd[CUT + j0]*sd[2*CUT + k0];
    float2 p0 = ph0s[i0];
    spl[idx] = pk2(prod*p0.x, prod*p0.y);
  }

  // ---- BS job decode: 392 jobs = (sector cell) x (fiber half of 7) ----
  int s = 0, csz = 1, pm = 0, gbase = 0, row = 0, col = 0, r0 = 0;
  const bool bs_act = (tid < 392);
  if (bs_act) {
    int jj = tid, cum = 0, ss = 0;
    for (ss = 0; ss < 27; ss++) {
      int cc = (ss < CUT) ? ss + 1 : 27 - ss;
      if (jj < cum + 2*cc) break;
      cum += 2*cc;
    }
    s   = ss;
    csz = (s < CUT) ? s + 1 : 27 - s;
    pm  = (s < CUT) ? 0 : s - 13;
    int q = jj - cum;
    int half = q / csz;
    int idxs = q % csz;
    r0  = half * 7;
    row = pm + idxs; col = s - row;
    int off = (s < CUT) ? s*(s+1)*(2*s+1)/6 : SECT - ((27-s)*(28-s)*(55-2*s))/6;
    gbase = off + idxs*csz;
  }
  const int in01 = (pm*13 + s)*CUT;         // mode01 input base (u stride 182)
  const int ob01 = (row*CUT + col)*CUT;     // mode01 output base
  const int in12 = pm*13 + s;               // mode12 input base (u stride 13)
  const int ob12 = row*CUT + col;           // mode12 output cell (i stride 196)

  const int m1s[3] = {0, 1, 0};   // PAIRS = [(0,1),(1,2),(0,1)]
  for (int l = 0; l < 2; l++) {
    for (int half_ = 0; half_ < 2; half_++) {
      const int gidbase = (circ*2 + l)*6 + half_*3;
      // =================== three REAL beamsplitter rotations ===================
      for (int p = 0; p < 3; p++) {
        const int gid = gidbase + p;
        {
          const float4* gm4 = (const float4*)g_bsR[gid];
          for (int ii = tid; ii < BSPAD/4; ii += NT) {
            float4 v = gm4[ii];
            sgd[4*ii+0] = pk2(v.x, v.x);
            sgd[4*ii+1] = pk2(v.y, v.y);
            sgd[4*ii+2] = pk2(v.z, v.z);
            sgd[4*ii+3] = pk2(v.w, v.w);
          }
          if (tid < CUT)          swr[tid]         = g_wrow[gid][tid];
          else if (tid < 2*CUT)   swc[tid - CUT]   = g_wcol[gid][tid - CUT];
          else if (tid < 3*CUT)   swf[tid - 2*CUT] = g_wfib[gid][tid - 2*CUT];
        }
        __syncthreads();
        unsigned long long acc[7];
        if (bs_act) {
          #pragma unroll
          for (int r = 0; r < 7; r++) acc[r] = 0ull;
          if (m1s[p] == 0) {          // contract axes (0,1); fiber axis 2 (stride 1)
            for (int u = 0; u < csz; u++) {
              unsigned long long w64 = sgd[gbase + u];
              const unsigned long long* f = spl + in01 + u*182 + r0;
              #pragma unroll
              for (int r = 0; r < 7; r++) acc[r] = f2fma(w64, f[r], acc[r]);
            }
          } else {                    // contract axes (1,2); fiber axis 0 (stride 196)
            for (int u = 0; u < csz; u++) {
              unsigned long long w64 = sgd[gbase + u];
              const unsigned long long* f = spl + in12 + u*13 + r0*196;
              #pragma unroll
              for (int r = 0; r < 7; r++) acc[r] = f2fma(w64, f[r*196], acc[r]);
            }
          }
        }
        __syncthreads();
        if (bs_act) {
          float2 wr = swr[row], wc = swc[col];
          float wbx = wr.x*wc.x - wr.y*wc.y;
          float wby = wr.x*wc.y + wr.y*wc.x;
          if (m1s[p] == 0) {
            unsigned long long* o = spl + ob01 + r0;
            #pragma unroll
            for (int r = 0; r < 7; r++) {
              float ax, ay; upk2(acc[r], ax, ay);
              o[r] = pk2(wbx*ax - wby*ay, wbx*ay + wby*ax);
            }
          } else {
            #pragma unroll
            for (int r = 0; r < 7; r++) {
              float2 wf = swf[r0 + r];
              float w2x = wbx*wf.x - wby*wf.y;
              float w2y = wbx*wf.y + wby*wf.x;
              float ax, ay; upk2(acc[r], ax, ay);
              spl[(r0 + r)*196 + ob12] = pk2(w2x*ax - w2y*ay, w2x*ay + w2y*ax);
            }
          }
        }
        // trailing sync REQUIRED: writeback READS swr/swc/swf which the next
        // staging overwrites (this race caused the R12 correctness failure).
        __syncthreads();
      }
      // ---- 3 REAL single-mode gates + writeback diagonal ----
      for (int m = 0; m < 3; m++) {
        const int u = gidbase + m;
        if (tid < 196) { float g = g_smR[u][tid]; sgd[tid] = pk2(g, g); }
        else if (tid < 196 + CUT) ssd[tid - 196] = g_sdiag[u][tid - 196];
        __syncthreads();
        if (half_ == 0) {
          // Sreal checkerboard: 392 jobs = (fiber f) x (parity P): 7 in -> 7 out
          unsigned long long o[7];
          int base = 0, stride = 1, P = 0;
          if (tid < 392) {
            int f = tid >> 1;
            P = tid & 1;
            if (m == 0)      { base = f;                       stride = 196; }
            else if (m == 1) { base = (f/CUT)*196 + (f%CUT);   stride = CUT; }
            else             { base = f*CUT;                   stride = 1;   }
            base += P*stride;
            unsigned long long fb[7];
            const unsigned long long* src = spl + base;
            #pragma unroll
            for (int t = 0; t < 7; t++) fb[t] = src[2*t*stride];
            #pragma unroll
            for (int a = 0; a < 7; a++) {
              unsigned long long acc2 = 0ull;
              #pragma unroll
              for (int t = 0; t < 7; t++)
                acc2 = f2fma(sgd[(P + 2*a)*CUT + P + 2*t], fb[t], acc2);
              o[a] = acc2;
            }
          }
          __syncthreads();
          if (tid < 392) {
            #pragma unroll
            for (int a = 0; a < 7; a++) {
              float2 d = ssd[P + 2*a];
              float ax, ay; upk2(o[a], ax, ay);
              spl[base + 2*a*stride] = pk2(d.x*ax - d.y*ay, d.x*ay + d.y*ax);
            }
          }
        } else {
          // Dreal dense: 392 jobs = (fiber f) x (output half h7)
          unsigned long long o[7];
          int base = 0, stride = 1, h7 = 0;
          if (tid < 392) {
            int f = tid >> 1;
            h7 = (tid & 1) * 7;
            if (m == 0)      { base = f;                       stride = 196; }
            else if (m == 1) { base = (f/CUT)*196 + (f%CUT);   stride = CUT; }
            else             { base = f*CUT;                   stride = 1;   }
            unsigned long long fb[CUT];
            #pragma unroll
            for (int t = 0; t < CUT; t++) fb[t] = spl[base + t*stride];
            #pragma unroll
            for (int a = 0; a < 7; a++) {
              unsigned long long acc2 = 0ull;
              #pragma unroll
              for (int t = 0; t < CUT; t++)
                acc2 = f2fma(sgd[(h7 + a)*CUT + t], fb[t], acc2);
              o[a] = acc2;
            }
          }
          __syncthreads();
          if (tid < 392) {
            #pragma unroll
            for (int a = 0; a < 7; a++) {
              float2 d = ssd[h7 + a];
              float ax, ay; upk2(o[a], ax, ay);
              spl[base + (h7 + a)*stride] = pk2(d.x*ax - d.y*ay, d.x*ay + d.y*ax);
            }
          }
        }
        // trailing sync REQUIRED: writeback READS ssd which the next staging
        // overwrites (same race class as the BS phase tables).
        __syncthreads();
      }
    }
  }

  // ---- expectations: single fused sweep for all 3 modes ----
  {
    float l0 = 0.f, l1 = 0.f, l2 = 0.f;
    for (int idx = tid; idx < DIM; idx += NT) {
      int i0 = idx / 196, rem = idx % 196;
      int j0 = rem / CUT, k0 = rem % CUT;
      float2 a2 = sp[idx];
      if (i0 < CUT-1) {
        float2 b2 = sp[idx + 196];
        l0 += sqrtf((float)(i0+1)) * (a2.x*b2.x + a2.y*b2.y);
      }
      if (j0 < CUT-1) {
        float2 b2 = sp[idx + CUT];
        l1 += sqrtf((float)(j0+1)) * (a2.x*b2.x + a2.y*b2.y);
      }
      if (k0 < CUT-1) {
        float2 b2 = sp[idx + 1];
        l2 += sqrtf((float)(k0+1)) * (a2.x*b2.x + a2.y*b2.y);
      }
    }
    #pragma unroll
    for (int o = 16; o > 0; o >>= 1) {
      l0 += __shfl_down_sync(0xffffffffu, l0, o);
      l1 += __shfl_down_sync(0xffffffffu, l1, o);
      l2 += __shfl_down_sync(0xffffffffu, l2, o);
    }
    if ((tid & 31) == 0) {
      sred[0][tid >> 5] = l0;
      sred[1][tid >> 5] = l1;
      sred[2][tid >> 5] = l2;
    }
    __syncthreads();
    if (tid < 3) {
      float tot = 0.f;
      #pragma unroll
      for (int w2 = 0; w2 < NT/32; w2++) tot += sred[tid][w2];
      out[b*6 + circ*3 + tid] = 2.f * tot;
    }
  }
}

// ================================ launch ================================
extern "C" void kernel_launch(void* const* d_in, const int* in_sizes, int n_in,
                              void* d_out, int out_size)
{
  (void)in_sizes; (void)n_in; (void)out_size;
  const float* x    = (const float*)d_in[0];
  const float* th1  = (const float*)d_in[1];
  const float* ph1  = (const float*)d_in[2];
  const float* vph1 = (const float*)d_in[3];
  const float* rr   = (const float*)d_in[4];
  const float* phr  = (const float*)d_in[5];
  const float* th2  = (const float*)d_in[6];
  const float* ph2  = (const float*)d_in[7];
  const float* vph2 = (const float*)d_in[8];
  const float* aa   = (const float*)d_in[9];
  const float* pha  = (const float*)d_in[10];
  const float* kk   = (const float*)d_in[11];

  gates_kernel<<<672, 196>>>(th1, ph1, vph1, rr, phr, th2, ph2, vph2, aa, pha, kk);
  dvec_kernel<<<24, 256>>>(x);
  dim3 grid(1024, 2);
  evolve_kernel<<<grid, NT>>>((float*)d_out);
}

// round 14
// speedup vs baseline: 1.0984x; 1.0984x over previous
#include <cuda_runtime.h>

#define CUT  14
#define DIM  2744          // 14^3
#define SECT 1834          // sum over sectors of c(s)^2
#define BSPAD 1840         // SECT padded to float4 multiple
#define NT   448           // evolve threads per CTA

// ---- dynamic smem layout (bytes) ----
#define SPL_OFF  0                      // u64[2744]            21952
#define SGD_OFF  21952                  // u64[2][1840]         29440
#define SPH_OFF  51392                  // float2[2][42]          672
#define PH0_OFF  52064                  // float2[14]             112
#define SD_OFF   52176                  // float[42]              168
#define SRED_OFF 52344                  // float[3][14]           168
#define SMEM_TOTAL 52512

// ---------------- persistent device scratch (no allocs allowed) ----------------
__device__ float  g_bsR[24][BSPAD];      // 24 BS gates: REAL sector-packed rotation
__device__ float  g_smR[24][CUT*CUT];    // 24 REAL single-mode gates (Sreal/Dreal)
__device__ float2 g_wrow[24][CUT];       // BS writeback phase (output row)
__device__ float2 g_wcol[24][CUT];       // BS writeback phase (output col)
__device__ float2 g_wfib[24][CUT];       // BS writeback phase (fiber; p1 only)
__device__ float2 g_sdiag[24][CUT];      // single-mode writeback diagonal
__device__ float2 g_init[2][CUT];        // initial-state phase on n0
__device__ float  g_dvec[2][1024][3][CUT]; // initial displacement vectors (real)

// ---------------- packed f32x2 helpers ----------------
__device__ __forceinline__ unsigned long long pk2(float lo, float hi) {
  unsigned long long r;
  asm("mov.b64 %0, {%1, %2};" : "=l"(r) : "f"(lo), "f"(hi));
  return r;
}
__device__ __forceinline__ void upk2(unsigned long long v, float& lo, float& hi) {
  asm("mov.b64 {%0, %1}, %2;" : "=f"(lo), "=f"(hi) : "l"(v));
}
__device__ __forceinline__ unsigned long long f2fma(unsigned long long a,
                                                    unsigned long long b,
                                                    unsigned long long c) {
  unsigned long long d;
  asm("fma.rn.f32x2 %0, %1, %2, %3;" : "=l"(d) : "l"(a), "l"(b), "l"(c));
  return d;
}

// ================= gate precompute: fp32 expm (s=8, terms=12, banded Taylor) =================
// ALL gates are real matrices; phases live in writeback-diagonal vectors:
//   BS:      U = e^{i phi n_m} Rreal e^{-i phi n_m}
//   squeeze: S = e^{i phr n/2} Sreal e^{-i phr n/2};  M1 = S*R(vph1)
//   disp:    D = e^{i pha n}   Dreal e^{-i pha n};    M2 = K*D*R(vph2)
__global__ void __launch_bounds__(196) gates_kernel(
    const float* __restrict__ th1, const float* __restrict__ ph1,
    const float* __restrict__ vph1, const float* __restrict__ rr,
    const float* __restrict__ phr, const float* __restrict__ th2,
    const float* __restrict__ ph2, const float* __restrict__ vph2,
    const float* __restrict__ aa, const float* __restrict__ pha,
    const float* __restrict__ kk)
{
  __shared__ float2 Bm[196], Ta[196], Tb[196], Ot[196];
  const int tid = threadIdx.x;
  const int i = tid / CUT, j = tid % CUT;
  const int task = blockIdx.x;

  int c = CUT, s = 0, pm = 0, gid = -1;
  double2 h = make_double2(0.0, 0.0);

  if (task < 648) {
    gid = task / 27; s = task % 27;
    pm = (s < CUT) ? 0 : s - (CUT-1);
    c  = (s < CUT) ? s + 1 : 2*CUT - 1 - s;
    int circ = gid / 12, rem = gid % 12;
    int l = rem / 6, w = (rem / 3) % 2, p = rem % 3;
    int b3 = (circ*2 + l)*3;
    double th = (double)((w ? th2 : th1)[b3 + p]);

    // writeback phase vectors (once per gate, via the s==0 block)
    if (s == 0 && tid < CUT) {
      const float* php = w ? ph2 : ph1;
      double f0 = (double)php[b3+0], f1v = (double)php[b3+1], f2v = (double)php[b3+2];
      double n = (double)tid;
      double dpn0, dpn1, dpn2;   // pre-diagonal angles of the NEXT single-mode gates
      if (w == 0) {
        dpn0 = ((double)vph1[b3+0] - 0.5*(double)phr[b3+0]) * n;
        dpn1 = ((double)vph1[b3+1] - 0.5*(double)phr[b3+1]) * n;
        dpn2 = ((double)vph1[b3+2] - 0.5*(double)phr[b3+2]) * n;
      } else {
        dpn0 = ((double)vph2[b3+0] - (double)pha[b3+0]) * n;
        dpn1 = ((double)vph2[b3+1] - (double)pha[b3+1]) * n;
        dpn2 = ((double)vph2[b3+2] - (double)pha[b3+2]) * n;
      }
      double ar, ac, af = 0.0;
      if (p == 0)      { ar = f0*n;          ac = -f1v*n; }
      else if (p == 1) { ar = f1v*n;         ac = dpn2;   af = -f2v*n; }
      else             { ar = f2v*n + dpn0;  ac = dpn1;   }
      g_wrow[gid][tid] = make_float2((float)cos(ar), (float)sin(ar));
      g_wcol[gid][tid] = make_float2((float)cos(ac), (float)sin(ac));
      g_wfib[gid][tid] = make_float2((float)cos(af), (float)sin(af));
      if (l == 0 && w == 0 && p == 0)
        g_init[circ][tid] = make_float2((float)cos(f0*n), (float)(-sin(f0*n)));
    }

    if (i < c && j < c) {
      int P = pm + i, Q = s - P;
      if (j == i - 1)      h.x =  th * sqrt((double)P * (double)(Q + 1));
      else if (j == i + 1) h.x = -th * sqrt((double)(P + 1) * (double)Q);
    }
  } else {
    int u = task - 648;
    int circ = u / 12, rem = u % 12;
    int l = rem / 6, w = (rem / 3) % 2, m = rem % 3;
    int pi = (circ*2 + l)*3 + m;
    if (w == 0) {  // Sreal = expm(r/2 (A^2 - Ad^2))
      double rv = (double)rr[pi];
      if (j == i + 2)      h.x =  0.5*sqrt((double)(i+1)*(double)(i+2))*rv;
      else if (i == j + 2) h.x = -0.5*sqrt((double)(j+1)*(double)(j+2))*rv;
    } else {       // Dreal = expm(a (Ad - A))
      double av = (double)aa[pi];
      if (i == j + 1)      h.x =  sqrt((double)j+1.0)*av;
      else if (j == i + 1) h.x = -sqrt((double)i+1.0)*av;
    }
    // writeback diagonal for this single-mode gate
    if (tid < CUT) {
      double n = (double)tid, ang;
      if (w == 0) {
        ang = 0.5*(double)phr[pi]*n;                    // post of S
        if (m == 0) ang -= (double)ph2[(circ*2 + l)*3 + 0]*n;  // pre of next BS set (mode0)
      } else {
        ang = (double)kk[pi]*n*n + (double)pha[pi]*n;   // K and post of D
        if (m == 0 && l == 0) ang -= (double)ph1[(circ*2 + 1)*3 + 0]*n;  // pre of layer-1 BS
      }
      g_sdiag[u][tid] = make_float2((float)cos(ang), (float)sin(ang));
    }
  }

  const bool act = (i < c && j < c);
  const double sc = 1.0/256.0;   // 2^-8
  Bm[tid] = make_float2((float)(h.x*sc), (float)(h.y*sc));
  float idv = (act && i == j) ? 1.0f : 0.0f;
  Ta[tid] = make_float2(idv, 0.0f);
  Ot[tid] = make_float2(idv, 0.0f);
  __syncthreads();

  const int t_lo = (j >= 2) ? j - 2 : 0;
  float2* term = Ta; float2* nxt = Tb;
  for (int k = 1; k <= 12; k++) {
    float2 acc = make_float2(0.f, 0.f);
    if (act) {
      int t_hi = (j + 2 < c - 1) ? j + 2 : c - 1;
      for (int t = t_lo; t <= t_hi; t++) {
        float2 xv = term[i*CUT + t], yv = Bm[t*CUT + j];
        acc.x += xv.x*yv.x - xv.y*yv.y;
        acc.y += xv.x*yv.y + xv.y*yv.x;
      }
      float inv = 1.0f/(float)k;
      acc.x *= inv; acc.y *= inv;
      nxt[i*CUT + j] = acc;
      Ot[i*CUT + j].x += acc.x;
      Ot[i*CUT + j].y += acc.y;
    }
    float2* z = term; term = nxt; nxt = z;
    __syncthreads();
  }
  for (int q = 0; q < 8; q++) {   // 8 squarings (2^8 scaling)
    float2 acc = make_float2(0.f, 0.f);
    if (act) {
      for (int t = 0; t < c; t++) {
        float2 xv = Ot[i*CUT + t], yv = Ot[t*CUT + j];
        acc.x += xv.x*yv.x - xv.y*yv.y;
        acc.y += xv.x*yv.y + xv.y*yv.x;
      }
    }
    __syncthreads();
    if (act) Ot[i*CUT + j] = acc;
    __syncthreads();
  }

  if (task < 648) {
    if (act) {
      int off = (s < CUT) ? s*(s+1)*(2*s+1)/6
                          : SECT - ((27-s)*(28-s)*(55-2*s))/6;
      g_bsR[gid][off + i*c + j] = Ot[tid].x;
    }
  } else {
    g_smR[task - 648][tid] = Ot[tid].x;
  }
}

// ============ initial displacement vectors: coherent-state closed form ============
__global__ void __launch_bounds__(256) dvec_kernel(const float* __restrict__ x)
{
  int tid = blockIdx.x*blockDim.x + threadIdx.x;
  if (tid >= 1024*6) return;
  int b = tid / 6, colx = tid % 6, circ = colx / 3, m = colx % 3;
  double xv = (double)x[tid];
  double c = exp(-0.5 * xv * xv);
  #pragma unroll
  for (int n = 0; n < CUT; n++) {
    g_dvec[circ][b][m][n] = (float)c;
    c *= xv * rsqrt((double)(n + 1));
  }
}

// -------- gate staging: strided cooperative copy into a (buf) region --------
__device__ __forceinline__ void stage_gate(
    int g, int circ, int t0, int tstr,
    unsigned long long* __restrict__ sgdb, float2* __restrict__ sphb)
{
  int l = g / 12, hf = (g % 12) / 6, slot = g % 6;
  int id = (circ*2 + l)*6 + hf*3 + (slot % 3);
  if (slot < 3) {
    const float4* gm4 = (const float4*)g_bsR[id];
    for (int ii = t0; ii < BSPAD/4; ii += tstr) {
      float4 v = gm4[ii];
      sgdb[4*ii+0] = pk2(v.x, v.x);
      sgdb[4*ii+1] = pk2(v.y, v.y);
      sgdb[4*ii+2] = pk2(v.z, v.z);
      sgdb[4*ii+3] = pk2(v.w, v.w);
    }
    for (int jj = t0; jj < 3*CUT; jj += tstr) {
      int which = jj / CUT, n = jj % CUT;
      sphb[jj] = (which == 0) ? g_wrow[id][n]
               : (which == 1) ? g_wcol[id][n] : g_wfib[id][n];
    }
  } else {
    for (int ii = t0; ii < CUT*CUT; ii += tstr) {
      float gv = g_smR[id][ii];
      sgdb[ii] = pk2(gv, gv);
    }
    for (int jj = t0; jj < CUT; jj += tstr) sphb[jj] = g_sdiag[id][jj];
  }
}

// ================= main evolution: one CTA per (batch, circuit) =================
// Pipeline: threads [0,392) compute gate g, threads [392,448) prefetch gate g+1
// into the other buffer. 2 barriers per gate phase; staging off critical path.
__global__ void __launch_bounds__(NT, 4) evolve_kernel(float* __restrict__ out)
{
  extern __shared__ char smem[];
  unsigned long long* spl = (unsigned long long*)(smem + SPL_OFF);
  unsigned long long* sgd = (unsigned long long*)(smem + SGD_OFF);
  float2* sph  = (float2*)(smem + SPH_OFF);
  float2* ph0s = (float2*)(smem + PH0_OFF);
  float*  sd   = (float*)(smem + SD_OFF);
  float*  sred = (float*)(smem + SRED_OFF);

  float2* sp = (float2*)spl;
  const int tid = threadIdx.x;
  const int b = blockIdx.x, circ = blockIdx.y;

  if (tid < 3*CUT) sd[tid] = g_dvec[circ][b][tid/CUT][tid%CUT];
  else if (tid < 4*CUT) ph0s[tid - 3*CUT] = g_init[circ][tid - 3*CUT];
  __syncthreads();
  for (int idx = tid; idx < DIM; idx += NT) {
    int i0 = idx / 196, j0 = (idx / CUT) % CUT, k0 = idx % CUT;
    float prod = sd[i0]*sd[CUT + j0]*sd[2*CUT + k0];
    float2 p0 = ph0s[i0];
    spl[idx] = pk2(prod*p0.x, prod*p0.y);
  }

  // ---- BS job decode: 392 jobs = (sector cell) x (fiber half of 7) ----
  int s = 0, csz = 1, pm = 0, gbase = 0, row = 0, col = 0, r0 = 0;
  const bool cmp_act = (tid < 392);
  if (cmp_act) {
    int jj = tid, cum = 0, ss = 0;
    for (ss = 0; ss < 27; ss++) {
      int cc = (ss < CUT) ? ss + 1 : 27 - ss;
      if (jj < cum + 2*cc) break;
      cum += 2*cc;
    }
    s   = ss;
    csz = (s < CUT) ? s + 1 : 27 - s;
    pm  = (s < CUT) ? 0 : s - 13;
    int q = jj - cum;
    int half = q / csz;
    int idxs = q % csz;
    r0  = half * 7;
    row = pm + idxs; col = s - row;
    int off = (s < CUT) ? s*(s+1)*(2*s+1)/6 : SECT - ((27-s)*(28-s)*(55-2*s))/6;
    gbase = off + idxs*csz;
  }
  const int in01 = (pm*13 + s)*CUT;         // mode01 input base (u stride 182)
  const int ob01 = (row*CUT + col)*CUT;     // mode01 output base
  const int in12 = pm*13 + s;               // mode12 input base (u stride 13)
  const int ob12 = row*CUT + col;           // mode12 output cell (i stride 196)

  // stage gate 0 cooperatively (all threads), then enter pipeline
  stage_gate(0, circ, tid, NT, sgd, sph);
  __syncthreads();

  for (int g = 0; g < 24; g++) {
    const int buf = g & 1;
    unsigned long long* sgdb = sgd + buf*BSPAD;
    float2* sphb = sph + buf*(3*CUT);
    const int hf = (g % 12) / 6, slot = g % 6;

    unsigned long long acc[7];
    int wbase = 0, wstride = 1, wsel = 0;

    if (cmp_act) {
      #pragma unroll
      for (int r = 0; r < 7; r++) acc[r] = 0ull;
      if (slot < 3) {
        if (slot != 1) {          // contract axes (0,1); fiber axis 2 (stride 1)
          for (int u = 0; u < csz; u++) {
            unsigned long long w64 = sgdb[gbase + u];
            const unsigned long long* f = spl + in01 + u*182 + r0;
            #pragma unroll
            for (int r = 0; r < 7; r++) acc[r] = f2fma(w64, f[r], acc[r]);
          }
        } else {                  // contract axes (1,2); fiber axis 0 (stride 196)
          for (int u = 0; u < csz; u++) {
            unsigned long long w64 = sgdb[gbase + u];
            const unsigned long long* f = spl + in12 + u*13 + r0*196;
            #pragma unroll
            for (int r = 0; r < 7; r++) acc[r] = f2fma(w64, f[r*196], acc[r]);
          }
        }
      } else {
        int m = slot - 3;
        int f = tid >> 1;
        if (m == 0)      { wbase = f;                       wstride = 196; }
        else if (m == 1) { wbase = (f/CUT)*196 + (f%CUT);   wstride = CUT; }
        else             { wbase = f*CUT;                   wstride = 1;   }
        if (hf == 0) {
          // Sreal checkerboard: parity split, t-outer (low register pressure)
          int P = tid & 1;
          wsel = P; wbase += P*wstride;
          for (int t = 0; t < 7; t++) {
            unsigned long long ft = spl[wbase + 2*t*wstride];
            #pragma unroll
            for (int a = 0; a < 7; a++)
              acc[a] = f2fma(sgdb[(P + 2*a)*CUT + P + 2*t], ft, acc[a]);
          }
        } else {
          // Dreal dense: output-half split, t-outer
          int h7 = (tid & 1) * 7;
          wsel = h7;
          for (int t = 0; t < CUT; t++) {
            unsigned long long ft = spl[wbase + t*wstride];
            #pragma unroll
            for (int a = 0; a < 7; a++)
              acc[a] = f2fma(sgdb[(h7 + a)*CUT + t], ft, acc[a]);
          }
        }
      }
    } else if (g + 1 < 24) {
      stage_gate(g + 1, circ, tid - 392, NT - 392,
                 sgd + (buf ^ 1)*BSPAD, sph + (buf ^ 1)*(3*CUT));
    }
    __syncthreads();   // compute reads of spl done; prefetch of g+1 done

    if (cmp_act) {
      if (slot < 3) {
        float2 wr = sphb[row], wc = sphb[CUT + col];
        float wbx = wr.x*wc.x - wr.y*wc.y;
        float wby = wr.x*wc.y + wr.y*wc.x;
        if (slot != 1) {
          unsigned long long* o = spl + ob01 + r0;
          #pragma unroll
          for (int r = 0; r < 7; r++) {
            float ax, ay; upk2(acc[r], ax, ay);
            o[r] = pk2(wbx*ax - wby*ay, wbx*ay + wby*ax);
          }
        } else {
          #pragma unroll
          for (int r = 0; r < 7; r++) {
            float2 wf = sphb[2*CUT + r0 + r];
            float w2x = wbx*wf.x - wby*wf.y;
            float w2y = wbx*wf.y + wby*wf.x;
            float ax, ay; upk2(acc[r], ax, ay);
            spl[(r0 + r)*196 + ob12] = pk2(w2x*ax - w2y*ay, w2x*ay + w2y*ax);
          }
        }
      } else {
        if (hf == 0) {
          #pragma unroll
          for (int a = 0; a < 7; a++) {
            float2 d = sphb[wsel + 2*a];
            float ax, ay; upk2(acc[a], ax, ay);
            spl[wbase + 2*a*wstride] = pk2(d.x*ax - d.y*ay, d.x*ay + d.y*ax);
          }
        } else {
          #pragma unroll
          for (int a = 0; a < 7; a++) {
            float2 d = sphb[wsel + a];
            float ax, ay; upk2(acc[a], ax, ay);
            spl[wbase + (wsel + a)*wstride] = pk2(d.x*ax - d.y*ay, d.x*ay + d.y*ax);
          }
        }
      }
    }
    __syncthreads();   // writeback done (and sphb reads done) before next phase
  }

  // ---- expectations: single fused sweep for all 3 modes ----
  {
    float l0 = 0.f, l1 = 0.f, l2 = 0.f;
    for (int idx = tid; idx < DIM; idx += NT) {
      int i0 = idx / 196, rem = idx % 196;
      int j0 = rem / CUT, k0 = rem % CUT;
      float2 a2 = sp[idx];
      if (i0 < CUT-1) {
        float2 b2 = sp[idx + 196];
        l0 += sqrtf((float)(i0+1)) * (a2.x*b2.x + a2.y*b2.y);
      }
      if (j0 < CUT-1) {
        float2 b2 = sp[idx + CUT];
        l1 += sqrtf((float)(j0+1)) * (a2.x*b2.x + a2.y*b2.y);
      }
      if (k0 < CUT-1) {
        float2 b2 = sp[idx + 1];
        l2 += sqrtf((float)(k0+1)) * (a2.x*b2.x + a2.y*b2.y);
      }
    }
    #pragma unroll
    for (int o = 16; o > 0; o >>= 1) {
      l0 += __shfl_down_sync(0xffffffffu, l0, o);
      l1 += __shfl_down_sync(0xffffffffu, l1, o);
      l2 += __shfl_down_sync(0xffffffffu, l2, o);
    }
    if ((tid & 31) == 0) {
      sred[0*(NT/32) + (tid >> 5)] = l0;
      sred[1*(NT/32) + (tid >> 5)] = l1;
      sred[2*(NT/32) + (tid >> 5)] = l2;
    }
    __syncthreads();
    if (tid < 3) {
      float tot = 0.f;
      #pragma unroll
      for (int w2 = 0; w2 < NT/32; w2++) tot += sred[tid*(NT/32) + w2];
      out[b*6 + circ*3 + tid] = 2.f * tot;
    }
  }
}

// ================================ launch ================================
extern "C" void kernel_launch(void* const* d_in, const int* in_sizes, int n_in,
                              void* d_out, int out_size)
{
  (void)in_sizes; (void)n_in; (void)out_size;
  const float* x    = (const float*)d_in[0];
  const float* th1  = (const float*)d_in[1];
  const float* ph1  = (const float*)d_in[2];
  const float* vph1 = (const float*)d_in[3];
  const float* rr   = (const float*)d_in[4];
  const float* phr  = (const float*)d_in[5];
  const float* th2  = (const float*)d_in[6];
  const float* ph2  = (const float*)d_in[7];
  const float* vph2 = (const float*)d_in[8];
  const float* aa   = (const float*)d_in[9];
  const float* pha  = (const float*)d_in[10];
  const float* kk   = (const float*)d_in[11];

  cudaFuncSetAttribute(evolve_kernel,
                       cudaFuncAttributeMaxDynamicSharedMemorySize, SMEM_TOTAL);

  gates_kernel<<<672, 196>>>(th1, ph1, vph1, rr, phr, th2, ph2, vph2, aa, pha, kk);
  dvec_kernel<<<24, 256>>>(x);
  dim3 grid(1024, 2);
  evolve_kernel<<<grid, NT, SMEM_TOTAL>>>((float*)d_out);
}